// round 1
// baseline (speedup 1.0000x reference)
#include <cuda_runtime.h>
#include <math.h>

// Problem constants
#define Bn   1024
#define Tn   512
#define Dn   64
#define Hn   256
#define Kn   320     // D + H
#define G4   1024    // 4*H
#define MIDn 64
#define An   3

// Tiling for the per-step gates GEMM
#define BM 64    // batch rows per CTA
#define UN 32    // hidden units per CTA -> 4*UN = 128 gate columns
#define CN 128   // gate columns per CTA
#define KC 32    // K chunk

// ---------------- device scratch (static, no allocation) ----------------
__device__ float g_Wr[Kn * G4];       // reordered weights: Wr[k][4u+g] = Wc[k][g*H+u]
__device__ float g_br[G4];            // reordered bias
__device__ float g_h[2][Bn * Hn];     // ping-pong hidden state
__device__ float g_c[Bn * Hn];
__device__ float g_n[Bn * Hn];
__device__ float g_a1[Bn * MIDn];
__device__ float g_v1[Bn * MIDn];

// ---------------- weight reorder + bias ----------------
__global__ void reorder_kernel(const float* __restrict__ Wc,
                               const float* __restrict__ bc) {
    int idx = blockIdx.x * blockDim.x + threadIdx.x;
    if (idx < Kn * G4) {
        int k   = idx / G4;
        int col = idx - k * G4;
        int u = col >> 2;
        int g = col & 3;
        g_Wr[idx] = Wc[k * G4 + g * Hn + u];
    }
    if (idx < G4) {
        int u = idx >> 2;
        int g = idx & 3;
        g_br[idx] = bc[g * Hn + u];
    }
}

// ---------------- state init ----------------
__global__ void init_kernel() {
    int idx = blockIdx.x * blockDim.x + threadIdx.x;
    if (idx < Bn * Hn) {
        g_h[0][idx] = 0.0f;
        g_c[idx]    = 0.0f;
        g_n[idx]    = 1.0f;
    }
}

// ---------------- fused per-timestep kernel: gates GEMM + sLSTM update ----------------
// grid: (Bn/BM = 16, Hn/UN = 8), block: 256 threads
// CTA (bi, ui): rows [bi*64, bi*64+64), units [ui*32, ui*32+32)
// thread: cg = tid&31 -> unit within tile (owns the i,f,o,z quad of that unit)
//         rg = tid>>5 -> 8 batch rows
__global__ __launch_bounds__(256, 1)
void step_kernel(const float* __restrict__ x, int t) {
    __shared__ float As[BM][KC + 1];   // [m][kk], padded stride 33 -> conflict free
    __shared__ float Bs[KC][CN];

    const float* __restrict__ hin  = g_h[t & 1];
    float* __restrict__       hout = g_h[(t + 1) & 1];

    int bi = blockIdx.x;
    int ui = blockIdx.y;
    int tid = threadIdx.x;
    int cg = tid & 31;
    int rg = tid >> 5;

    int row0 = bi * BM;
    int col0 = ui * CN;   // in reordered gate-column space

    float acc[8][4];
#pragma unroll
    for (int r = 0; r < 8; r++)
#pragma unroll
        for (int q = 0; q < 4; q++) acc[r][q] = 0.0f;

    for (int kc = 0; kc < Kn; kc += KC) {
        // load A chunk: 64 rows x 32 k (x for k<64, h otherwise)
#pragma unroll
        for (int i = 0; i < 8; i++) {
            int flat = tid + i * 256;
            int m  = flat >> 5;
            int kk = flat & 31;
            int kg = kc + kk;
            float v;
            if (kg < Dn)
                v = x[(size_t)(row0 + m) * (Tn * Dn) + (size_t)t * Dn + kg];
            else
                v = hin[(row0 + m) * Hn + (kg - Dn)];
            As[m][kk] = v;
        }
        // load B chunk: 32 k x 128 cols
#pragma unroll
        for (int i = 0; i < 16; i++) {
            int flat = tid + i * 256;
            int kk = flat >> 7;
            int n  = flat & 127;
            Bs[kk][n] = g_Wr[(kc + kk) * G4 + col0 + n];
        }
        __syncthreads();

#pragma unroll 8
        for (int kk = 0; kk < KC; kk++) {
            float4 w = *(const float4*)&Bs[kk][cg * 4];
#pragma unroll
            for (int r = 0; r < 8; r++) {
                float a = As[rg * 8 + r][kk];
                acc[r][0] = fmaf(a, w.x, acc[r][0]);
                acc[r][1] = fmaf(a, w.y, acc[r][1]);
                acc[r][2] = fmaf(a, w.z, acc[r][2]);
                acc[r][3] = fmaf(a, w.w, acc[r][3]);
            }
        }
        __syncthreads();
    }

    // epilogue: sLSTM gate math + state update
    int u = ui * UN + cg;           // global hidden unit
    float b0 = g_br[col0 + cg * 4 + 0];
    float b1 = g_br[col0 + cg * 4 + 1];
    float b2 = g_br[col0 + cg * 4 + 2];
    float b3 = g_br[col0 + cg * 4 + 3];

#pragma unroll
    for (int r = 0; r < 8; r++) {
        int b = row0 + rg * 8 + r;
        int sidx = b * Hn + u;

        float gi = acc[r][0] + b0;
        float gf = acc[r][1] + b1;
        float go = acc[r][2] + b2;
        float gz = acc[r][3] + b3;

        gi = fminf(fmaxf(gi, -5.0f), 5.0f);
        gf = fminf(fmaxf(gf, -5.0f), 5.0f);
        float iv = expf(gi);
        float fv = expf(gf);

        float cv = fv * g_c[sidx] + iv * tanhf(gz);
        cv = fminf(fmaxf(cv, -1e6f), 1e6f);
        float nv = fv * g_n[sidx] + iv;
        nv = fminf(fmaxf(nv, 1e-6f), 1e6f);
        g_c[sidx] = cv;
        g_n[sidx] = nv;

        float ov = 1.0f / (1.0f + expf(-go));
        float hv = ov * (cv / nv);
        if (!isfinite(hv)) hv = 0.0f;
        hout[sidx] = hv;
    }
}

// ---------------- heads: layer 1 (h @ Wa1, h @ Wv1, relu) ----------------
__global__ void heads1_kernel(const float* __restrict__ Wa1,
                              const float* __restrict__ ba1,
                              const float* __restrict__ Wv1,
                              const float* __restrict__ bv1) {
    int idx = blockIdx.x * blockDim.x + threadIdx.x;  // 0 .. Bn*128-1
    if (idx >= Bn * 128) return;
    int b = idx >> 7;
    int j = idx & 127;
    const float* hrow = g_h[Tn & 1] + b * Hn;   // final h lives in g_h[0]
    if (j < MIDn) {
        float s = ba1[j];
#pragma unroll 8
        for (int k = 0; k < Hn; k++) s = fmaf(hrow[k], Wa1[k * MIDn + j], s);
        g_a1[b * MIDn + j] = fmaxf(s, 0.0f);
    } else {
        int jj = j - MIDn;
        float s = bv1[jj];
#pragma unroll 8
        for (int k = 0; k < Hn; k++) s = fmaf(hrow[k], Wv1[k * MIDn + jj], s);
        g_v1[b * MIDn + jj] = fmaxf(s, 0.0f);
    }
}

// ---------------- heads: layer 2 (logits + softmax, value) ----------------
__global__ void heads2_kernel(const float* __restrict__ Wa2,
                              const float* __restrict__ ba2,
                              const float* __restrict__ Wv2,
                              const float* __restrict__ bv2,
                              float* __restrict__ out) {
    int b = blockIdx.x * blockDim.x + threadIdx.x;
    if (b >= Bn) return;
    float l0 = ba2[0], l1 = ba2[1], l2 = ba2[2];
#pragma unroll 8
    for (int m = 0; m < MIDn; m++) {
        float a = g_a1[b * MIDn + m];
        l0 = fmaf(a, Wa2[m * An + 0], l0);
        l1 = fmaf(a, Wa2[m * An + 1], l1);
        l2 = fmaf(a, Wa2[m * An + 2], l2);
    }
    float mx = fmaxf(l0, fmaxf(l1, l2));
    float e0 = expf(l0 - mx), e1 = expf(l1 - mx), e2 = expf(l2 - mx);
    float s = e0 + e1 + e2;
    out[b * An + 0] = e0 / s;
    out[b * An + 1] = e1 / s;
    out[b * An + 2] = e2 / s;

    float v = bv2[0];
#pragma unroll 8
    for (int m = 0; m < MIDn; m++) v = fmaf(g_v1[b * MIDn + m], Wv2[m], v);
    out[Bn * An + b] = v;
}

// ---------------- launch ----------------
extern "C" void kernel_launch(void* const* d_in, const int* in_sizes, int n_in,
                              void* d_out, int out_size) {
    const float* x   = (const float*)d_in[0];
    const float* Wc  = (const float*)d_in[1];
    const float* bc  = (const float*)d_in[2];
    const float* Wa1 = (const float*)d_in[3];
    const float* ba1 = (const float*)d_in[4];
    const float* Wa2 = (const float*)d_in[5];
    const float* ba2 = (const float*)d_in[6];
    const float* Wv1 = (const float*)d_in[7];
    const float* bv1 = (const float*)d_in[8];
    const float* Wv2 = (const float*)d_in[9];
    const float* bv2 = (const float*)d_in[10];
    float* out = (float*)d_out;

    reorder_kernel<<<(Kn * G4 + 255) / 256, 256>>>(Wc, bc);
    init_kernel<<<(Bn * Hn + 255) / 256, 256>>>();

    dim3 grid(Bn / BM, Hn / UN);   // (16, 8) = 128 CTAs
    for (int t = 0; t < Tn; t++) {
        step_kernel<<<grid, 256>>>(x, t);
    }

    heads1_kernel<<<(Bn * 128 + 255) / 256, 256>>>(Wa1, ba1, Wv1, bv1);
    heads2_kernel<<<(Bn + 255) / 256, 256>>>(Wa2, ba2, Wv2, bv2, out);
}

// round 3
// speedup vs baseline: 1.1140x; 1.1140x over previous
#include <cuda_runtime.h>
#include <cuda_bf16.h>
#include <math.h>

// Problem constants
#define Bn   1024
#define Tn   512
#define Dn   64
#define Hn   256
#define Kn   320     // D + H
#define G4   1024    // 4*H
#define MIDn 64
#define An   3

// Tiling
#define CTA_M  128
#define CTA_N  64
#define KC     32      // k elements per chunk
#define NK2    16      // bf16-pairs (uint32) per chunk
#define APITCH 136     // 136 mod 32 == 8 -> conflict-free frag loads
#define BPITCH 72      // 72  mod 32 == 8
#define CPAD   68

// ---------------- device scratch (static, no allocation) ----------------
// k-space ordering: k 0..255 = h (Wc rows 64+k), k 256..319 = x (Wc rows k-256)
__device__ unsigned g_WT[3][160][1024];      // [plane][k2][gatecol] bf16 pair along k
__device__ unsigned g_xT[3][Tn][32][1024];   // [plane][t][d2][b]
__device__ unsigned g_hT[2][3][128][1024];   // [buf][plane][u2][b]
__device__ float g_br[G4];
__device__ float g_hfull[Bn * Hn];
__device__ float g_c[Bn * Hn];
__device__ float g_n[Bn * Hn];
__device__ float g_a1[Bn * MIDn];
__device__ float g_v1[Bn * MIDn];

// ---------------- helpers ----------------
__device__ __forceinline__ void split3(float v, __nv_bfloat16& b1,
                                       __nv_bfloat16& b2, __nv_bfloat16& b3) {
    b1 = __float2bfloat16(v);
    float r = v - __bfloat162float(b1);
    b2 = __float2bfloat16(r);
    float r2 = r - __bfloat162float(b2);
    b3 = __float2bfloat16(r2);
}

__device__ __forceinline__ unsigned packbf(__nv_bfloat16 lo_k, __nv_bfloat16 hi_k) {
    __nv_bfloat162 p;
    p.x = lo_k;   // even k in low 16 bits
    p.y = hi_k;   // odd k in high 16 bits
    return *(unsigned*)&p;
}

__device__ __forceinline__ void mma_bf16(float c[4], const unsigned a[4], const unsigned b[2]) {
    asm volatile(
        "mma.sync.aligned.m16n8k16.row.col.f32.bf16.bf16.f32 "
        "{%0,%1,%2,%3}, {%4,%5,%6,%7}, {%8,%9}, {%0,%1,%2,%3};"
        : "+f"(c[0]), "+f"(c[1]), "+f"(c[2]), "+f"(c[3])
        : "r"(a[0]), "r"(a[1]), "r"(a[2]), "r"(a[3]), "r"(b[0]), "r"(b[1]));
}

// ---------------- weight reorder + split + bias ----------------
__global__ void reorder_kernel(const float* __restrict__ Wc,
                               const float* __restrict__ bc) {
    int idx = blockIdx.x * blockDim.x + threadIdx.x;
    if (idx < 160 * 1024) {
        int k2 = idx >> 10;
        int n  = idx & 1023;
        int u = n >> 2, g = n & 3;
        int col = g * Hn + u;
        int k0 = 2 * k2, k1 = k0 + 1;
        int r0 = (k0 < 256) ? (64 + k0) : (k0 - 256);
        int r1 = (k1 < 256) ? (64 + k1) : (k1 - 256);
        float w0 = Wc[r0 * G4 + col];
        float w1 = Wc[r1 * G4 + col];
        __nv_bfloat16 s0[3], s1[3];
        split3(w0, s0[0], s0[1], s0[2]);
        split3(w1, s1[0], s1[1], s1[2]);
#pragma unroll
        for (int p = 0; p < 3; p++)
            g_WT[p][k2][n] = packbf(s0[p], s1[p]);
    }
    if (idx < G4) {
        int u = idx >> 2, g = idx & 3;
        g_br[idx] = bc[g * Hn + u];
    }
}

// ---------------- x reformat: split + pack + transpose ----------------
__global__ void xsplit_kernel(const float* __restrict__ x) {
    int idx = blockIdx.x * blockDim.x + threadIdx.x;  // Tn*32*Bn = 16.8M
    int b = idx & 1023;
    int rest = idx >> 10;
    int d2 = rest & 31;
    int t = rest >> 5;
    if (t >= Tn) return;
    float v0 = x[((size_t)b * Tn + t) * Dn + 2 * d2];
    float v1 = x[((size_t)b * Tn + t) * Dn + 2 * d2 + 1];
    __nv_bfloat16 s0[3], s1[3];
    split3(v0, s0[0], s0[1], s0[2]);
    split3(v1, s1[0], s1[1], s1[2]);
#pragma unroll
    for (int p = 0; p < 3; p++)
        g_xT[p][t][d2][b] = packbf(s0[p], s1[p]);
}

// ---------------- state init ----------------
__global__ void init_kernel() {
    int idx = blockIdx.x * blockDim.x + threadIdx.x;
    if (idx < 3 * 128 * 1024)
        ((unsigned*)g_hT)[idx] = 0u;     // buffer 0, all planes
    if (idx < Bn * Hn) {
        g_c[idx] = 0.0f;
        g_n[idx] = 1.0f;
    }
}

// ---------------- fused per-timestep kernel: bf16x6 GEMM + sLSTM update ----------------
// grid (8, 16) = 128 CTAs, 256 threads (8 warps), warp tile 32x32
__global__ __launch_bounds__(256, 1)
void step_kernel(int t) {
    extern __shared__ unsigned smem_u[];
    unsigned* sA = smem_u;                         // [3][NK2][APITCH]
    unsigned* sB = smem_u + 3 * NK2 * APITCH;      // [3][NK2][BPITCH]
    float*    Cs = (float*)smem_u;                 // epilogue staging [128][CPAD]

    const int tid  = threadIdx.x;
    const int lane = tid & 31;
    const int warp = tid >> 5;
    const int wm = warp & 3;
    const int wn = warp >> 2;
    const int gid = lane >> 2;   // 0..7
    const int tig = lane & 3;    // 0..3

    const int row0 = blockIdx.x * CTA_M;
    const int col0 = blockIdx.y * CTA_N;
    const int cur = t & 1, nxt = (t + 1) & 1;

    float cm[2][4][4];   // main term a1*b1
    float cl[2][4][4];   // low-order terms
#pragma unroll
    for (int mi = 0; mi < 2; mi++)
#pragma unroll
        for (int ni = 0; ni < 4; ni++)
#pragma unroll
            for (int q = 0; q < 4; q++) { cm[mi][ni][q] = 0.0f; cl[mi][ni][q] = 0.0f; }

    for (int kc2 = 0; kc2 < 160; kc2 += NK2) {
        // ---- load A chunk: 3 planes x 16 k2 x 128 m ----
#pragma unroll
        for (int i = 0; i < 24; i++) {
            int flat = i * 256 + tid;
            int m  = flat & 127;
            int pk = flat >> 7;          // 0..47
            int p  = pk >> 4;
            int k2 = pk & 15;
            int k2g = kc2 + k2;
            const unsigned* src = (k2g < 128) ? &g_hT[cur][p][k2g][row0]
                                              : &g_xT[p][t][k2g - 128][row0];
            sA[(p * NK2 + k2) * APITCH + m] = src[m];
        }
        // ---- load B chunk: 3 planes x 16 k2 x 64 n ----
#pragma unroll
        for (int i = 0; i < 12; i++) {
            int flat = i * 256 + tid;
            int n  = flat & 63;
            int pk = flat >> 6;          // 0..47
            int p  = pk >> 4;
            int k2 = pk & 15;
            sB[(p * NK2 + k2) * BPITCH + n] = g_WT[p][kc2 + k2][col0 + n];
        }
        __syncthreads();

#pragma unroll
        for (int ks = 0; ks < 2; ks++) {
            int kb = ks * 8;
            unsigned a[3][2][4];
#pragma unroll
            for (int p = 0; p < 3; p++)
#pragma unroll
                for (int mi = 0; mi < 2; mi++) {
                    const unsigned* ab = sA + p * NK2 * APITCH;
                    int m0 = wm * 32 + mi * 16;
                    a[p][mi][0] = ab[(kb + tig)     * APITCH + m0 + gid];
                    a[p][mi][1] = ab[(kb + tig)     * APITCH + m0 + 8 + gid];
                    a[p][mi][2] = ab[(kb + tig + 4) * APITCH + m0 + gid];
                    a[p][mi][3] = ab[(kb + tig + 4) * APITCH + m0 + 8 + gid];
                }
            unsigned b[3][4][2];
#pragma unroll
            for (int p = 0; p < 3; p++)
#pragma unroll
                for (int ni = 0; ni < 4; ni++) {
                    const unsigned* bb = sB + p * NK2 * BPITCH;
                    int n0 = wn * 32 + ni * 8;
                    b[p][ni][0] = bb[(kb + tig)     * BPITCH + n0 + gid];
                    b[p][ni][1] = bb[(kb + tig + 4) * BPITCH + n0 + gid];
                }
#pragma unroll
            for (int mi = 0; mi < 2; mi++)
#pragma unroll
                for (int ni = 0; ni < 4; ni++) {
                    mma_bf16(cm[mi][ni], a[0][mi], b[0][ni]);  // hi*hi
                    mma_bf16(cl[mi][ni], a[0][mi], b[1][ni]);  // hi*mid
                    mma_bf16(cl[mi][ni], a[1][mi], b[0][ni]);  // mid*hi
                    mma_bf16(cl[mi][ni], a[0][mi], b[2][ni]);  // hi*lo
                    mma_bf16(cl[mi][ni], a[1][mi], b[1][ni]);  // mid*mid
                    mma_bf16(cl[mi][ni], a[2][mi], b[0][ni]);  // lo*hi
                }
        }
        __syncthreads();
    }

    // ---- stage C through smem to regroup (i,f,o,z) quads ----
#pragma unroll
    for (int mi = 0; mi < 2; mi++)
#pragma unroll
        for (int ni = 0; ni < 4; ni++) {
            int row = wm * 32 + mi * 16 + gid;
            int col = wn * 32 + ni * 8 + tig * 2;
            Cs[row * CPAD + col]           = cm[mi][ni][0] + cl[mi][ni][0];
            Cs[row * CPAD + col + 1]       = cm[mi][ni][1] + cl[mi][ni][1];
            Cs[(row + 8) * CPAD + col]     = cm[mi][ni][2] + cl[mi][ni][2];
            Cs[(row + 8) * CPAD + col + 1] = cm[mi][ni][3] + cl[mi][ni][3];
        }
    __syncthreads();

    // ---- pass 1: read gates into registers ----
    float4 gq[8];
#pragma unroll
    for (int i = 0; i < 8; i++) {
        int qflat = i * 256 + tid;
        int row = qflat >> 4;
        int ql  = qflat & 15;
        gq[i] = *(const float4*)&Cs[row * CPAD + ql * 4];
    }
    __syncthreads();   // Cs dead -> reuse smem for Hs

    __nv_bfloat16* Hs = (__nv_bfloat16*)smem_u;  // [3][128][16]

    const bool last = (t == Tn - 1);
#pragma unroll
    for (int i = 0; i < 8; i++) {
        int qflat = i * 256 + tid;
        int row = qflat >> 4;
        int ql  = qflat & 15;
        float4 bv = *(const float4*)&g_br[col0 + ql * 4];

        float gi = gq[i].x + bv.x;
        float gf = gq[i].y + bv.y;
        float go = gq[i].z + bv.z;
        float gz = gq[i].w + bv.w;

        gi = fminf(fmaxf(gi, -5.0f), 5.0f);
        gf = fminf(fmaxf(gf, -5.0f), 5.0f);
        float iv = expf(gi);
        float fv = expf(gf);

        int b = row0 + row;
        int u = (col0 >> 2) + ql;
        int sidx = b * Hn + u;

        float cv = fv * g_c[sidx] + iv * tanhf(gz);
        cv = fminf(fmaxf(cv, -1e6f), 1e6f);
        float nv = fv * g_n[sidx] + iv;
        nv = fminf(fmaxf(nv, 1e-6f), 1e6f);
        g_c[sidx] = cv;
        g_n[sidx] = nv;

        float ov = 1.0f / (1.0f + expf(-go));
        float hv = ov * (cv / nv);
        if (!isfinite(hv)) hv = 0.0f;

        __nv_bfloat16 h1, h2, h3;
        split3(hv, h1, h2, h3);
        Hs[(0 * 128 + row) * 16 + ql] = h1;
        Hs[(1 * 128 + row) * 16 + ql] = h2;
        Hs[(2 * 128 + row) * 16 + ql] = h3;
        if (last) g_hfull[sidx] = hv;
    }
    __syncthreads();

    // ---- packed h global write: 3 planes x 8 u2 x 128 b ----
#pragma unroll
    for (int i = 0; i < 12; i++) {
        int flat = i * 256 + tid;
        int m  = flat & 127;
        int pu = flat >> 7;    // 0..23
        int p   = pu >> 3;
        int u2l = pu & 7;
        __nv_bfloat16 e = Hs[(p * 128 + m) * 16 + u2l * 2];
        __nv_bfloat16 o = Hs[(p * 128 + m) * 16 + u2l * 2 + 1];
        g_hT[nxt][p][(col0 >> 3) + u2l][row0 + m] = packbf(e, o);
    }
}

// ---------------- heads ----------------
__global__ void heads1_kernel(const float* __restrict__ Wa1,
                              const float* __restrict__ ba1,
                              const float* __restrict__ Wv1,
                              const float* __restrict__ bv1) {
    int idx = blockIdx.x * blockDim.x + threadIdx.x;
    if (idx >= Bn * 128) return;
    int b = idx >> 7;
    int j = idx & 127;
    const float* hrow = g_hfull + b * Hn;
    if (j < MIDn) {
        float s = ba1[j];
#pragma unroll 8
        for (int k = 0; k < Hn; k++) s = fmaf(hrow[k], Wa1[k * MIDn + j], s);
        g_a1[b * MIDn + j] = fmaxf(s, 0.0f);
    } else {
        int jj = j - MIDn;
        float s = bv1[jj];
#pragma unroll 8
        for (int k = 0; k < Hn; k++) s = fmaf(hrow[k], Wv1[k * MIDn + jj], s);
        g_v1[b * MIDn + jj] = fmaxf(s, 0.0f);
    }
}

__global__ void heads2_kernel(const float* __restrict__ Wa2,
                              const float* __restrict__ ba2,
                              const float* __restrict__ Wv2,
                              const float* __restrict__ bv2,
                              float* __restrict__ out) {
    int b = blockIdx.x * blockDim.x + threadIdx.x;
    if (b >= Bn) return;
    float l0 = ba2[0], l1 = ba2[1], l2 = ba2[2];
#pragma unroll 8
    for (int m = 0; m < MIDn; m++) {
        float a = g_a1[b * MIDn + m];
        l0 = fmaf(a, Wa2[m * An + 0], l0);
        l1 = fmaf(a, Wa2[m * An + 1], l1);
        l2 = fmaf(a, Wa2[m * An + 2], l2);
    }
    float mx = fmaxf(l0, fmaxf(l1, l2));
    float e0 = expf(l0 - mx), e1 = expf(l1 - mx), e2 = expf(l2 - mx);
    float s = e0 + e1 + e2;
    out[b * An + 0] = e0 / s;
    out[b * An + 1] = e1 / s;
    out[b * An + 2] = e2 / s;

    float v = bv2[0];
#pragma unroll 8
    for (int m = 0; m < MIDn; m++) v = fmaf(g_v1[b * MIDn + m], Wv2[m], v);
    out[Bn * An + b] = v;
}

// ---------------- launch ----------------
extern "C" void kernel_launch(void* const* d_in, const int* in_sizes, int n_in,
                              void* d_out, int out_size) {
    const float* x   = (const float*)d_in[0];
    const float* Wc  = (const float*)d_in[1];
    const float* bc  = (const float*)d_in[2];
    const float* Wa1 = (const float*)d_in[3];
    const float* ba1 = (const float*)d_in[4];
    const float* Wa2 = (const float*)d_in[5];
    const float* ba2 = (const float*)d_in[6];
    const float* Wv1 = (const float*)d_in[7];
    const float* bv1 = (const float*)d_in[8];
    const float* Wv2 = (const float*)d_in[9];
    const float* bv2 = (const float*)d_in[10];
    float* out = (float*)d_out;

    const int smem_bytes = (3 * NK2 * APITCH + 3 * NK2 * BPITCH) * 4;  // 39936 B

    reorder_kernel<<<(160 * 1024 + 255) / 256, 256>>>(Wc, bc);
    xsplit_kernel<<<(Tn * 32 * Bn + 255) / 256, 256>>>(x);
    init_kernel<<<(3 * 128 * 1024 + 255) / 256, 256>>>();

    dim3 grid(Bn / CTA_M, G4 / CTA_N);   // (8, 16)
    for (int t = 0; t < Tn; t++) {
        step_kernel<<<grid, 256, smem_bytes>>>(t);
    }

    heads1_kernel<<<(Bn * 128 + 255) / 256, 256>>>(Wa1, ba1, Wv1, bv1);
    heads2_kernel<<<(Bn + 255) / 256, 256>>>(Wa2, ba2, Wv2, bv2, out);
}

// round 5
// speedup vs baseline: 1.4649x; 1.3150x over previous
#include <cuda_runtime.h>
#include <cuda_bf16.h>
#include <math.h>
#include <stdint.h>

// Problem constants
#define Bn   1024
#define Tn   512
#define Dn   64
#define Hn   256
#define G4   1024
#define MIDn 64
#define An   3

// Persistent-kernel tiling: CTA = 128 rows x 64 gate-cols, K=320 in 10 chunks of 32
#define APITCH 80        // A smem row pitch bytes (32k * 2B + 16 pad) -> conflict-free ldmatrix
#define BPITCH 656       // B smem row pitch bytes (320k * 2B + 16 pad)
#define ABUF   (3*128*APITCH)          // 30720 B per A buffer (3 planes)
#define BS_OFF (2*ABUF)                // 61440
#define SMEM_TOT (BS_OFF + 3*64*BPITCH)  // 61440 + 125952 = 187392

// ---------------- device scratch (static, no allocation) ----------------
__device__ __nv_bfloat16 g_W[3][G4][320];          // [plane][gatecol][k]
__device__ __nv_bfloat16 g_x[3][Bn][Tn][Dn];       // split x, 192 MB
__device__ __nv_bfloat16 g_h[2][3][Bn][Hn];        // ping-pong split h
__device__ float g_br[G4];
__device__ float g_hfull[Bn*Hn];
__device__ float g_a1[Bn*MIDn];
__device__ float g_v1[Bn*MIDn];
__device__ int   g_bar[8];                          // per-bi barrier counters

// ---------------- helpers ----------------
__device__ __forceinline__ void split3(float v, __nv_bfloat16& b1,
                                       __nv_bfloat16& b2, __nv_bfloat16& b3) {
    b1 = __float2bfloat16(v);
    float r = v - __bfloat162float(b1);
    b2 = __float2bfloat16(r);
    float r2 = r - __bfloat162float(b2);
    b3 = __float2bfloat16(r2);
}

__device__ __forceinline__ uint32_t smem_u32(const void* p) {
    uint32_t a;
    asm("{ .reg .u64 t; cvta.to.shared.u64 t, %1; cvt.u32.u64 %0, t; }" : "=r"(a) : "l"(p));
    return a;
}

__device__ __forceinline__ void cp16(uint32_t dst, const void* src) {
    asm volatile("cp.async.cg.shared.global [%0], [%1], 16;" :: "r"(dst), "l"(src) : "memory");
}
__device__ __forceinline__ void cp_commit() {
    asm volatile("cp.async.commit_group;" ::: "memory");
}

#define LDSM4(R, addr) \
    asm volatile("ldmatrix.sync.aligned.m8n8.x4.shared.b16 {%0,%1,%2,%3}, [%4];" \
        : "=r"((R)[0]), "=r"((R)[1]), "=r"((R)[2]), "=r"((R)[3]) : "r"(addr))

__device__ __forceinline__ void mma_bf16(float c[4], const uint32_t a[4],
                                         uint32_t b0, uint32_t b1) {
    asm volatile(
        "mma.sync.aligned.m16n8k16.row.col.f32.bf16.bf16.f32 "
        "{%0,%1,%2,%3}, {%4,%5,%6,%7}, {%8,%9}, {%0,%1,%2,%3};"
        : "+f"(c[0]), "+f"(c[1]), "+f"(c[2]), "+f"(c[3])
        : "r"(a[0]), "r"(a[1]), "r"(a[2]), "r"(a[3]), "r"(b0), "r"(b1));
}

// ---------------- prep: weight reorder + split + bias ----------------
// k-space: k 0..255 = h units (Wc rows 64+k), k 256..319 = x dims (Wc rows k-256)
__global__ void wsplit_kernel(const float* __restrict__ Wc, const float* __restrict__ bc) {
    int idx = blockIdx.x * blockDim.x + threadIdx.x;   // 1024*320
    if (idx < G4 * 320) {
        int k = idx % 320;
        int gcol = idx / 320;
        int u = gcol >> 2, g = gcol & 3;
        int r = (k < 256) ? (64 + k) : (k - 256);
        float w = Wc[r * G4 + g * Hn + u];
        __nv_bfloat16 s[3];
        split3(w, s[0], s[1], s[2]);
#pragma unroll
        for (int p = 0; p < 3; p++) g_W[p][gcol][k] = s[p];
    }
    if (idx < G4) {
        int u = idx >> 2, g = idx & 3;
        g_br[idx] = bc[g * Hn + u];
    }
}

// ---------------- prep: x split ----------------
__global__ void xsplit_kernel(const float* __restrict__ x) {
    int idx = blockIdx.x * blockDim.x + threadIdx.x;   // 1024*512*64
    int d = idx & 63;
    int tt = (idx >> 6) & 511;
    int b = idx >> 15;
    if (b >= Bn) return;
    float v = x[((size_t)b * Tn + tt) * Dn + d];
    __nv_bfloat16 s[3];
    split3(v, s[0], s[1], s[2]);
#pragma unroll
    for (int p = 0; p < 3; p++) g_x[p][b][tt][d] = s[p];
}

// ---------------- prep: init ----------------
__global__ void init_kernel() {
    int idx = blockIdx.x * blockDim.x + threadIdx.x;
    if (idx < 3 * Bn * Hn / 2)
        ((unsigned*)g_h[0])[idx] = 0u;    // h_0 = 0 (all 3 planes)
    if (idx < 8) g_bar[idx] = 0;
}

// ---------------- persistent step kernel ----------------
// grid (8, 16): bi = blockIdx.x (128 batch rows), ci = blockIdx.y (16 units)
__global__ __launch_bounds__(256, 1)
void step_kernel() {
    extern __shared__ char dsm[];
    const uint32_t sbase = smem_u32(dsm);

    const int tid  = threadIdx.x;
    const int lane = tid & 31;
    const int warp = tid >> 5;
    const int wm = warp & 3;      // 4 warps in m
    const int wn = warp >> 2;     // 2 warps in n
    const int bi = blockIdx.x;
    const int ci = blockIdx.y;
    const int row0 = bi * 128;

    // ---- load resident B (weights) once: 3 planes x 64 rows x 640B ----
    for (int i = 0; i < 30; i++) {
        int flat = i * 256 + tid;            // < 7680
        int q = flat % 40;
        int n = (flat / 40) & 63;
        int p = flat / (40 * 64);
        uint32_t dst = sbase + BS_OFF + (uint32_t)(p * 64 + n) * BPITCH + q * 16;
        const char* src = (const char*)&g_W[p][ci * 64 + n][q * 8];
        cp16(dst, src);
    }
    cp_commit();

    // ---- per-thread recurrent state in registers ----
    float cold[8], nold[8];
#pragma unroll
    for (int q = 0; q < 8; q++) { cold[q] = 0.0f; nold[q] = 1.0f; }

    // fragment address components
    const int mrow = lane & 15;
    const int kAo  = (lane >> 4) << 3;                      // 0 or 8
    const int nBo  = ((lane >> 4) << 3) + (lane & 7);       // 0..15
    const int kBo  = ((lane >> 3) & 1) << 3;                // 0 or 8
    const bool odd = lane & 1;
    const int jh = (lane >> 1) & 1;                          // unit select within ni

    for (int t = 0; t < Tn; t++) {
        const int hbuf = t & 1;

        // ---- A chunk producer (cp.async 16B x 6 per thread) ----
        auto issue_chunk = [&](int ch, int buf) {
#pragma unroll
            for (int i = 0; i < 6; i++) {
                int flat = i * 256 + tid;     // < 1536
                int q = flat & 3;
                int m = (flat >> 2) & 127;
                int p = flat >> 9;
                uint32_t dst = sbase + (uint32_t)(buf * 3 + p) * (128 * APITCH)
                             + (uint32_t)m * APITCH + q * 16;
                const char* src;
                if (ch < 8)
                    src = (const char*)&g_h[hbuf][p][row0 + m][ch * 32 + q * 8];
                else
                    src = (const char*)&g_x[p][row0 + m][t][(ch - 8) * 32 + q * 8];
                cp16(dst, src);
            }
            cp_commit();
        };

        float cm[2][4][4], cl[2][4][4];
#pragma unroll
        for (int mi = 0; mi < 2; mi++)
#pragma unroll
            for (int ni = 0; ni < 4; ni++)
#pragma unroll
                for (int q = 0; q < 4; q++) { cm[mi][ni][q] = 0.0f; cl[mi][ni][q] = 0.0f; }

        issue_chunk(0, 0);
        issue_chunk(1, 1);

#pragma unroll 1
        for (int ch = 0; ch < 10; ch++) {
            if (ch == 9) asm volatile("cp.async.wait_group 0;" ::: "memory");
            else         asm volatile("cp.async.wait_group 1;" ::: "memory");
            __syncthreads();

            const int buf = ch & 1;
            const uint32_t abase = sbase + (uint32_t)buf * ABUF;
            const uint32_t bkoff = (uint32_t)(ch * 32) * 2;

#pragma unroll
            for (int ks = 0; ks < 32; ks += 16) {
                uint32_t a[3][2][4], bf[3][2][4];
#pragma unroll
                for (int p = 0; p < 3; p++) {
#pragma unroll
                    for (int mi = 0; mi < 2; mi++) {
                        uint32_t ad = abase + (uint32_t)(p * 128 + wm * 32 + mi * 16 + mrow) * APITCH
                                    + (ks + kAo) * 2;
                        LDSM4(a[p][mi], ad);
                    }
#pragma unroll
                    for (int pr = 0; pr < 2; pr++) {
                        uint32_t bd = sbase + BS_OFF
                                    + (uint32_t)(p * 64 + wn * 32 + pr * 16 + nBo) * BPITCH
                                    + bkoff + (ks + kBo) * 2;
                        LDSM4(bf[p][pr], bd);
                    }
                }
#pragma unroll
                for (int mi = 0; mi < 2; mi++)
#pragma unroll
                    for (int ni = 0; ni < 4; ni++) {
                        const int pr = ni >> 1, o = (ni & 1) * 2;
                        mma_bf16(cm[mi][ni], a[0][mi], bf[0][pr][o], bf[0][pr][o+1]); // hi*hi
                        mma_bf16(cl[mi][ni], a[0][mi], bf[1][pr][o], bf[1][pr][o+1]); // hi*mid
                        mma_bf16(cl[mi][ni], a[1][mi], bf[0][pr][o], bf[0][pr][o+1]); // mid*hi
                        mma_bf16(cl[mi][ni], a[0][mi], bf[2][pr][o], bf[2][pr][o+1]); // hi*lo
                        mma_bf16(cl[mi][ni], a[1][mi], bf[1][pr][o], bf[1][pr][o+1]); // mid*mid
                        mma_bf16(cl[mi][ni], a[2][mi], bf[0][pr][o], bf[0][pr][o+1]); // lo*hi
                    }
            }
            __syncthreads();
            if (ch + 2 < 10) issue_chunk(ch + 2, buf);
        }

        // ---- epilogue: shuffle-regroup quads, gate math, h split ----
        __nv_bfloat16* Hs = (__nv_bfloat16*)dsm;   // [3][128][16], aliases buf0 (free now)
        const bool last = (t == Tn - 1);

#pragma unroll
        for (int mi = 0; mi < 2; mi++)
#pragma unroll
            for (int ni = 0; ni < 4; ni++) {
                float q0 = cm[mi][ni][0] + cl[mi][ni][0];
                float q1 = cm[mi][ni][1] + cl[mi][ni][1];
                float q2 = cm[mi][ni][2] + cl[mi][ni][2];
                float q3 = cm[mi][ni][3] + cl[mi][ni][3];
                float s0 = __shfl_xor_sync(0xFFFFFFFFu, q0, 1);
                float s1 = __shfl_xor_sync(0xFFFFFFFFu, q1, 1);
                float s2 = __shfl_xor_sync(0xFFFFFFFFu, q2, 1);
                float s3 = __shfl_xor_sync(0xFFFFFFFFu, q3, 1);

                float gi = odd ? s2 : q0;
                float gf = odd ? s3 : q1;
                float go = odd ? q2 : s0;
                float gz = odd ? q3 : s1;

                const int row = wm * 32 + mi * 16 + (lane >> 2) + (odd ? 8 : 0);
                const int ul  = wn * 8 + ni * 2 + jh;
                const int qi  = mi * 4 + ni;

                float4 bq = *(const float4*)&g_br[ci * 64 + ul * 4];
                gi += bq.x; gf += bq.y; go += bq.z; gz += bq.w;

                gi = fminf(fmaxf(gi, -5.0f), 5.0f);
                gf = fminf(fmaxf(gf, -5.0f), 5.0f);
                float iv = expf(gi);
                float fv = expf(gf);

                float cv = fv * cold[qi] + iv * tanhf(gz);
                cv = fminf(fmaxf(cv, -1e6f), 1e6f);
                float nv = fv * nold[qi] + iv;
                nv = fminf(fmaxf(nv, 1e-6f), 1e6f);
                cold[qi] = cv;
                nold[qi] = nv;

                float ov = 1.0f / (1.0f + expf(-go));
                float hv = ov * (cv / nv);
                if (!isfinite(hv)) hv = 0.0f;

                __nv_bfloat16 h1, h2, h3;
                split3(hv, h1, h2, h3);
                Hs[(0 * 128 + row) * 16 + ul] = h1;
                Hs[(1 * 128 + row) * 16 + ul] = h2;
                Hs[(2 * 128 + row) * 16 + ul] = h3;
                if (last) g_hfull[(row0 + row) * Hn + ci * 16 + ul] = hv;
            }
        __syncthreads();

        if (!last) {
            // coalesced h writeback: 3 planes x 128 rows x 32B
            const int nbuf = hbuf ^ 1;
#pragma unroll
            for (int i = 0; i < 3; i++) {
                int flat = i * 256 + tid;      // < 768
                int q = flat & 1;
                int m = (flat >> 1) & 127;
                int p = flat >> 8;
                uint4 v = *(const uint4*)&Hs[(p * 128 + m) * 16 + q * 8];
                *(uint4*)&g_h[nbuf][p][row0 + m][ci * 16 + q * 8] = v;
            }
            // per-bi grid barrier (16 CTAs share this h slice)
            __threadfence();
            __syncthreads();
            if (tid == 0) {
                atomicAdd(&g_bar[bi], 1);
                const int target = 16 * (t + 1);
                while (((volatile int*)g_bar)[bi] < target) { }
                __threadfence();
            }
            __syncthreads();
        }
    }
}

// ---------------- heads ----------------
__global__ void heads1_kernel(const float* __restrict__ Wa1, const float* __restrict__ ba1,
                              const float* __restrict__ Wv1, const float* __restrict__ bv1) {
    int idx = blockIdx.x * blockDim.x + threadIdx.x;
    if (idx >= Bn * 128) return;
    int b = idx >> 7;
    int j = idx & 127;
    const float* hrow = g_hfull + b * Hn;
    if (j < MIDn) {
        float s = ba1[j];
#pragma unroll 8
        for (int k = 0; k < Hn; k++) s = fmaf(hrow[k], Wa1[k * MIDn + j], s);
        g_a1[b * MIDn + j] = fmaxf(s, 0.0f);
    } else {
        int jj = j - MIDn;
        float s = bv1[jj];
#pragma unroll 8
        for (int k = 0; k < Hn; k++) s = fmaf(hrow[k], Wv1[k * MIDn + jj], s);
        g_v1[b * MIDn + jj] = fmaxf(s, 0.0f);
    }
}

__global__ void heads2_kernel(const float* __restrict__ Wa2, const float* __restrict__ ba2,
                              const float* __restrict__ Wv2, const float* __restrict__ bv2,
                              float* __restrict__ out) {
    int b = blockIdx.x * blockDim.x + threadIdx.x;
    if (b >= Bn) return;
    float l0 = ba2[0], l1 = ba2[1], l2 = ba2[2];
#pragma unroll 8
    for (int m = 0; m < MIDn; m++) {
        float a = g_a1[b * MIDn + m];
        l0 = fmaf(a, Wa2[m * An + 0], l0);
        l1 = fmaf(a, Wa2[m * An + 1], l1);
        l2 = fmaf(a, Wa2[m * An + 2], l2);
    }
    float mx = fmaxf(l0, fmaxf(l1, l2));
    float e0 = expf(l0 - mx), e1 = expf(l1 - mx), e2 = expf(l2 - mx);
    float s = e0 + e1 + e2;
    out[b * An + 0] = e0 / s;
    out[b * An + 1] = e1 / s;
    out[b * An + 2] = e2 / s;

    float v = bv2[0];
#pragma unroll 8
    for (int m = 0; m < MIDn; m++) v = fmaf(g_v1[b * MIDn + m], Wv2[m], v);
    out[Bn * An + b] = v;
}

// ---------------- launch ----------------
extern "C" void kernel_launch(void* const* d_in, const int* in_sizes, int n_in,
                              void* d_out, int out_size) {
    const float* x   = (const float*)d_in[0];
    const float* Wc  = (const float*)d_in[1];
    const float* bc  = (const float*)d_in[2];
    const float* Wa1 = (const float*)d_in[3];
    const float* ba1 = (const float*)d_in[4];
    const float* Wa2 = (const float*)d_in[5];
    const float* ba2 = (const float*)d_in[6];
    const float* Wv1 = (const float*)d_in[7];
    const float* bv1 = (const float*)d_in[8];
    const float* Wv2 = (const float*)d_in[9];
    const float* bv2 = (const float*)d_in[10];
    float* out = (float*)d_out;

    cudaFuncSetAttribute(step_kernel, cudaFuncAttributeMaxDynamicSharedMemorySize, SMEM_TOT);

    wsplit_kernel<<<(G4 * 320 + 255) / 256, 256>>>(Wc, bc);
    xsplit_kernel<<<(Bn * Tn * Dn + 255) / 256, 256>>>(x);
    init_kernel<<<(3 * Bn * Hn / 2 + 255) / 256, 256>>>();

    step_kernel<<<dim3(8, 16), 256, SMEM_TOT>>>();

    heads1_kernel<<<(Bn * 128 + 255) / 256, 256>>>(Wa1, ba1, Wv1, bv1);
    heads2_kernel<<<(Bn + 255) / 256, 256>>>(Wa2, ba2, Wv2, bv2, out);
}